// round 13
// baseline (speedup 1.0000x reference)
#include <cuda_runtime.h>
#include <cuda_fp16.h>
#include <cstdint>

#define N_HT   21
#define NBLK   (32 * 3 * N_HT)          // 2016 partial sums
#define POOL_COUNT 59535.0f             // 15*63*63
#define X_ELEMS  (32*3*32*128*128)
#define W_ELEMS  (16*81)
#define N_CO     16

#define SROWB    272                    // bytes per smem row (136 halfs)
#define ROW3     (3 * SROWB)            // 816
#define SLOTMUL  (8 * ROW3)             // 6528
#define TILE_BYTES (120 * ROW3)         // 97,920 (3ci x 5slot x 8r trows)
#define RAW_OFF  TILE_BYTES
#define SMEM_BYTES (TILE_BYTES + 24 * 512)   // +12,288 raw = 110,208
#define TAIL_T0  (82 * ROW3 + 2 * SROWB)     // k=80: ci=2(*40) + kh=2, kw=2

__device__ float    g_scratch[NBLK];
__device__ int      g_is_f32;
__device__ unsigned g_wfrag[32 * 24];   // B fragments, ks 0..4 used
__device__ unsigned g_bias2[32 * 2];
__device__ unsigned g_w81[32 * 2];      // per-lane half2 of weight k=80 per ntile

// ---------------------------------------------------------------------------
__global__ void prep_kernel(const unsigned short* __restrict__ xb,
                            const void* __restrict__ cwr,
                            const void* __restrict__ cbr)
{
    int bad = 0;
    #pragma unroll
    for (int j = 0; j < 8; ++j) {
        unsigned v = xb[threadIdx.x + j * 256];
        if (((v >> 10) & 0x1F) >= 21) bad = 1;
    }
    const int isf32 = __syncthreads_or(bad) ? 1 : 0;
    if (threadIdx.x == 0) g_is_f32 = isf32;

    if (threadIdx.x >= 32) return;
    const int l = threadIdx.x;
    const int q = l & 3;
    const int g = l >> 2;
    #pragma unroll
    for (int ks = 0; ks < 6; ++ks)
        #pragma unroll
        for (int nt = 0; nt < 2; ++nt) {
            const int co = nt * 8 + g;
            __half v[4];
            #pragma unroll
            for (int j = 0; j < 4; ++j) {
                int k = ks * 16 + 2 * q + ((j >> 1) * 8) + (j & 1);
                float w = 0.f;
                if (k < 81)
                    w = isf32 ? ((const float*)cwr)[co * 81 + k]
                              : __half2float(((const __half*)cwr)[co * 81 + k]);
                v[j] = __float2half(w);
            }
            __half2 p0 = __halves2half2(v[0], v[1]);
            __half2 p1 = __halves2half2(v[2], v[3]);
            g_wfrag[l * 24 + (ks * 2 + nt) * 2 + 0] = *reinterpret_cast<unsigned*>(&p0);
            g_wfrag[l * 24 + (ks * 2 + nt) * 2 + 1] = *reinterpret_cast<unsigned*>(&p1);
        }
    #pragma unroll
    for (int nt = 0; nt < 2; ++nt) {
        const int c0 = nt * 8 + 2 * q;
        float b0 = isf32 ? ((const float*)cbr)[c0]
                         : __half2float(((const __half*)cbr)[c0]);
        float b1 = isf32 ? ((const float*)cbr)[c0 + 1]
                         : __half2float(((const __half*)cbr)[c0 + 1]);
        __half2 bb = __floats2half2_rn(b0, b1);
        g_bias2[l * 2 + nt] = *reinterpret_cast<unsigned*>(&bb);

        float w0 = isf32 ? ((const float*)cwr)[c0 * 81 + 80]
                         : __half2float(((const __half*)cwr)[c0 * 81 + 80]);
        float w1 = isf32 ? ((const float*)cwr)[(c0 + 1) * 81 + 80]
                         : __half2float(((const __half*)cwr)[(c0 + 1) * 81 + 80]);
        __half2 ww = __floats2half2_rn(w0, w1);
        g_w81[l * 2 + nt] = *reinterpret_cast<unsigned*>(&ww);
    }
}

// ---------------------------------------------------------------------------
#define LDSM4(dst, addr)                                                    \
    asm volatile(                                                           \
        "ldmatrix.sync.aligned.m8n8.x4.trans.shared.b16 {%0,%1,%2,%3}, [%4];" \
        : "=r"((dst)[0]), "=r"((dst)[1]), "=r"((dst)[2]), "=r"((dst)[3])    \
        : "r"(addr))

#define HMMA16(c0, c1, aa, b0, b1)                                          \
    asm volatile(                                                           \
        "mma.sync.aligned.m16n8k16.row.col.f16.f16.f16.f16 "                \
        "{%0,%1}, {%2,%3,%4,%5}, {%6,%7}, {%0,%1};"                         \
        : "+r"(c0), "+r"(c1)                                                \
        : "r"((aa)[0]), "r"((aa)[1]), "r"((aa)[2]), "r"((aa)[3]),           \
          "r"(b0), "r"(b1))

#define CPA16(saddr, gaddr)                                                 \
    asm volatile("cp.async.cg.shared.global [%0], [%1], 16;"                \
                 :: "r"(saddr), "l"(gaddr) : "memory")

__device__ __forceinline__ void sts_shifts(char* sA, int trow, int t2,
                                           unsigned h0r, unsigned h1r,
                                           unsigned h2r, unsigned h3r)
{
    unsigned n0 = __shfl_down_sync(0xffffffffu, h0r, 1);
    if (t2 == 15) n0 = 0u;
    const int base = trow * ROW3 + t2 * 16;
    *reinterpret_cast<uint4*>(sA + base) = make_uint4(h0r, h1r, h2r, h3r);
    unsigned p0 = __byte_perm(h0r, h1r, 0x5432);
    unsigned p1 = __byte_perm(h1r, h2r, 0x5432);
    unsigned p2 = __byte_perm(h2r, h3r, 0x5432);
    unsigned p3 = __byte_perm(h3r, n0,  0x5432);
    *reinterpret_cast<uint4*>(sA + base + SROWB) = make_uint4(p0, p1, p2, p3);
    *reinterpret_cast<uint4*>(sA + base + 2 * SROWB) = make_uint4(h1r, h2r, h3r, n0);
}

__global__ __launch_bounds__(192, 2) void conv_mma_kernel(
    const void* __restrict__ xr)
{
    extern __shared__ __align__(16) char sA[];
    __shared__ float swsum[6];

    const int tid = threadIdx.x;
    const int wi  = tid >> 5;
    const int l   = tid & 31;
    const int ht  = blockIdx.x;
    const int hf  = blockIdx.y;          // 0,1,2
    const int b   = blockIdx.z;
    const int isf32 = g_is_f32;

    const int ndp = 5;
    const int db  = hf * 10;             // db % 5 == 0
    const int h0  = ht * 6;

    uint32_t sab;
    asm("{ .reg .u64 t; cvta.to.shared.u64 t, %1; cvt.u32.u64 %0, t; }"
        : "=r"(sab) : "l"(sA));

    // --- persistent B fragments (5 ksteps), bias, tail weights ---
    unsigned bfr[20];
    {
        const uint4* wf = reinterpret_cast<const uint4*>(&g_wfrag[l * 24]);
        #pragma unroll
        for (int i = 0; i < 5; ++i) {
            uint4 u = wf[i];
            bfr[i*4+0] = u.x; bfr[i*4+1] = u.y; bfr[i*4+2] = u.z; bfr[i*4+3] = u.w;
        }
    }
    unsigned bias2[2] = { g_bias2[l * 2], g_bias2[l * 2 + 1] };
    unsigned w81r[2]  = { g_w81[l * 2],  g_w81[l * 2 + 1] };

    // --- prologue: stage depths db..db+3 into slots 0..3, batched loads ---
    const int t2 = l & 15;
    if (isf32) {
        uint4 raw[8][2];
        #pragma unroll
        for (int it = 0; it < 8; ++it) {
            const int row = wi * 16 + it * 2 + (l >> 4);
            const int ci = row >> 5, dzi = (row >> 3) & 3, r = row & 7;
            const long goff =
                ((long)((b * 3 + ci) * 32 + db + dzi) * 128 + (h0 + r)) * 128 + t2 * 8;
            const uint4* gp = reinterpret_cast<const uint4*>((const float*)xr + goff);
            raw[it][0] = gp[0];
            raw[it][1] = gp[1];
        }
        #pragma unroll
        for (int it = 0; it < 8; ++it) {
            const int row = wi * 16 + it * 2 + (l >> 4);
            const int ci = row >> 5, dzi = (row >> 3) & 3, r = row & 7;
            const int trow = (ci * 5 + dzi) * 8 + r;
            float4 f0 = *reinterpret_cast<float4*>(&raw[it][0]);
            float4 f1 = *reinterpret_cast<float4*>(&raw[it][1]);
            __half2 a = __floats2half2_rn(f0.x, f0.y);
            __half2 c = __floats2half2_rn(f0.z, f0.w);
            __half2 e = __floats2half2_rn(f1.x, f1.y);
            __half2 g = __floats2half2_rn(f1.z, f1.w);
            sts_shifts(sA, trow, t2,
                       *reinterpret_cast<unsigned*>(&a),
                       *reinterpret_cast<unsigned*>(&c),
                       *reinterpret_cast<unsigned*>(&e),
                       *reinterpret_cast<unsigned*>(&g));
        }
    } else {
        uint4 raw[8];
        #pragma unroll
        for (int it = 0; it < 8; ++it) {
            const int row = wi * 16 + it * 2 + (l >> 4);
            const int ci = row >> 5, dzi = (row >> 3) & 3, r = row & 7;
            const long goff =
                ((long)((b * 3 + ci) * 32 + db + dzi) * 128 + (h0 + r)) * 128 + t2 * 8;
            raw[it] = *reinterpret_cast<const uint4*>((const __half*)xr + goff);
        }
        #pragma unroll
        for (int it = 0; it < 8; ++it) {
            const int row = wi * 16 + it * 2 + (l >> 4);
            const int ci = row >> 5, dzi = (row >> 3) & 3, r = row & 7;
            const int trow = (ci * 5 + dzi) * 8 + r;
            sts_shifts(sA, trow, t2, raw[it].x, raw[it].y, raw[it].z, raw[it].w);
        }
    }
    __syncthreads();

    // --- per-lane k decomposition (k = 0..79, no padding) ---
    const int hp    = wi % 3;
    const int mhalf = wi / 3;
    const unsigned klocal = (unsigned)((l & 7) | ((l & 16) >> 1));
    const unsigned wbyte  = (unsigned)((l & 8) << 1);
    const unsigned m0b    = (unsigned)(mhalf * 128);

    unsigned rowbase[5];
    int kdv[5];
    #pragma unroll
    for (int ks = 0; ks < 5; ++ks) {
        const int k = ks * 16 + (int)klocal;       // < 80, always valid
        int ci = k / 27;  int rm = k - ci * 27;
        int kd = rm / 9;  rm -= kd * 9;
        int kh = rm / 3;  int kw = rm - kh * 3;
        rowbase[ks] = (unsigned)((ci * 40 + kh) * ROW3 + kw * SROWB);
        kdv[ks] = kd;
    }

    unsigned pm01[4][2], pm23[4][2];
    #pragma unroll
    for (int mt = 0; mt < 4; ++mt)
        #pragma unroll
        for (int nt = 0; nt < 2; ++nt) { pm01[mt][nt] = 0u; pm23[mt][nt] = 0u; }

    const __half2 z2 = __float2half2_rn(0.f);
    const bool v23ok = !(mhalf == 1 && (l >> 2) >= 6);
    float s = 0.f;

    // =================== depth-rolling main loop (5-slot ring) ===========
    #pragma unroll 1
    for (int dpi = 0; dpi < ndp; ++dpi) {
        const bool nxt = (dpi + 1 < ndp);
        const int b5 = (2 * dpi) % 5;

        #pragma unroll
        for (int dd = 0; dd < 2; ++dd) {
            // --- prefetch one depth into raw buffer ---
            const int dnew = db + 2 * dpi + 4 + dd;
            if (nxt) {
                if (isf32) {
                    #pragma unroll
                    for (int p = 0; p < 4; ++p) {
                        const int c  = tid + p * 192;   // 0..767
                        const int rr = c >> 5;          // 0..23
                        const int ch = c & 31;
                        const char* g = (const char*)xr +
                            (((long)((b * 3 + (rr >> 3)) * 32 + dnew) * 128
                              + (h0 + (rr & 7))) * 128) * 4 + ch * 16;
                        CPA16(sab + RAW_OFF + rr * 512 + ch * 16, g);
                    }
                } else {
                    #pragma unroll
                    for (int p = 0; p < 2; ++p) {
                        const int c  = tid + p * 192;   // 0..383
                        const int rr = c >> 4;
                        const int ch = c & 15;
                        const char* g = (const char*)xr +
                            (((long)((b * 3 + (rr >> 3)) * 32 + dnew) * 128
                              + (h0 + (rr & 7))) * 128) * 2 + ch * 16;
                        CPA16(sab + RAW_OFF + rr * 256 + ch * 16, g);
                    }
                }
                asm volatile("cp.async.commit_group;" ::: "memory");
            }

            // --- slot-resolved row offsets for this dd ---
            unsigned rowb[5];
            #pragma unroll
            for (int ks = 0; ks < 5; ++ks) {
                int s5 = b5 + dd + kdv[ks];
                if (s5 >= 5) s5 -= 5;
                rowb[ks] = rowbase[ks] + (unsigned)(s5 * SLOTMUL);
            }
            int st5 = b5 + dd + 2;
            if (st5 >= 5) st5 -= 5;
            const unsigned tailoff = (unsigned)TAIL_T0 + (unsigned)(st5 * SLOTMUL);

            // ---- 2 GEMMs: h2 = 0,1 ----
            #pragma unroll 1
            for (int h2 = 0; h2 < 2; ++h2) {
                const int hh = hp * 2 + h2;
                const unsigned abase = sab + (unsigned)(hh * ROW3) + wbyte + m0b;
                unsigned c01[4][2], c23[4][2];
                #pragma unroll
                for (int mt = 0; mt < 4; ++mt)
                    #pragma unroll
                    for (int nt = 0; nt < 2; ++nt) { c01[mt][nt] = 0u; c23[mt][nt] = 0u; }

                unsigned afr[2][4][4];
                #pragma unroll
                for (int mt = 0; mt < 4; ++mt)
                    LDSM4(afr[0][mt], abase + rowb[0] + mt * 32);

                #pragma unroll
                for (int ks = 0; ks < 5; ++ks) {
                    const int cur = ks & 1;
                    if (ks < 4) {
                        #pragma unroll
                        for (int mt = 0; mt < 4; ++mt)
                            LDSM4(afr[cur ^ 1][mt], abase + rowb[ks + 1] + mt * 32);
                    }
                    const unsigned b0 = bfr[(ks * 2 + 0) * 2 + 0];
                    const unsigned b1 = bfr[(ks * 2 + 0) * 2 + 1];
                    const unsigned b2 = bfr[(ks * 2 + 1) * 2 + 0];
                    const unsigned b3 = bfr[(ks * 2 + 1) * 2 + 1];
                    #pragma unroll
                    for (int mt = 0; mt < 4; ++mt) {
                        HMMA16(c01[mt][0], c23[mt][0], afr[cur][mt], b0, b1);
                        HMMA16(c01[mt][1], c23[mt][1], afr[cur][mt], b2, b3);
                    }
                }

                // ---- tail tap k=80: rank-1 update ----
                {
                    const int toff = (int)tailoff + hh * ROW3
                                   + (int)m0b + ((l >> 2) << 1);
                    #pragma unroll
                    for (int mt = 0; mt < 4; ++mt) {
                        __half x0 = *reinterpret_cast<const __half*>(
                            sA + toff + mt * 32);
                        __half x1 = *reinterpret_cast<const __half*>(
                            sA + toff + mt * 32 + 16);
                        __half2 x00 = __half2half2(x0);
                        __half2 x11 = __half2half2(x1);
                        #pragma unroll
                        for (int nt = 0; nt < 2; ++nt) {
                            __half2 ww = *reinterpret_cast<__half2*>(&w81r[nt]);
                            __half2 cc0 = *reinterpret_cast<__half2*>(&c01[mt][nt]);
                            __half2 cc1 = *reinterpret_cast<__half2*>(&c23[mt][nt]);
                            cc0 = __hfma2(x00, ww, cc0);
                            cc1 = __hfma2(x11, ww, cc1);
                            c01[mt][nt] = *reinterpret_cast<unsigned*>(&cc0);
                            c23[mt][nt] = *reinterpret_cast<unsigned*>(&cc1);
                        }
                    }
                }

                // +bias, relu, fold into pooled max
                #pragma unroll
                for (int mt = 0; mt < 4; ++mt)
                    #pragma unroll
                    for (int nt = 0; nt < 2; ++nt) {
                        __half2 bb = *reinterpret_cast<__half2*>(&bias2[nt]);
                        __half2 h01 = __hmax2(__hadd2(
                            *reinterpret_cast<__half2*>(&c01[mt][nt]), bb), z2);
                        __half2 h23 = __hmax2(__hadd2(
                            *reinterpret_cast<__half2*>(&c23[mt][nt]), bb), z2);
                        __half2 p0 = *reinterpret_cast<__half2*>(&pm01[mt][nt]);
                        __half2 p1 = *reinterpret_cast<__half2*>(&pm23[mt][nt]);
                        p0 = __hmax2(p0, h01);
                        p1 = __hmax2(p1, h23);
                        pm01[mt][nt] = *reinterpret_cast<unsigned*>(&p0);
                        pm23[mt][nt] = *reinterpret_cast<unsigned*>(&p1);
                    }
            }

            // ---- after dd=1: per-dp pooling extract ----
            if (dd == 1) {
                #pragma unroll
                for (int mt = 0; mt < 4; ++mt)
                    #pragma unroll
                    for (int nt = 0; nt < 2; ++nt) {
                        unsigned q01 = pm01[mt][nt];
                        unsigned o01 = __shfl_xor_sync(0xffffffffu, q01, 4);
                        __half2 m01 = __hmax2(*reinterpret_cast<__half2*>(&q01),
                                              *reinterpret_cast<__half2*>(&o01));
                        float2 f01 = __half22float2(m01);
                        s += f01.x + f01.y;

                        unsigned q23 = pm23[mt][nt];
                        unsigned o23 = __shfl_xor_sync(0xffffffffu, q23, 4);
                        __half2 m23 = __hmax2(*reinterpret_cast<__half2*>(&q23),
                                              *reinterpret_cast<__half2*>(&o23));
                        if (mt != 3 || v23ok) {
                            float2 f23 = __half22float2(m23);
                            s += f23.x + f23.y;
                        }
                        pm01[mt][nt] = 0u;
                        pm23[mt][nt] = 0u;
                    }
            }

            // ---- drain prefetch, convert raw -> free slot (overlaps GEMMs
            //      of this phase in other warps; target slot unread) ----
            if (nxt) {
                asm volatile("cp.async.wait_group 0;" ::: "memory");
                const int slot = (dd == 0) ? ((b5 + 4 >= 5) ? b5 - 1 : b5 + 4)
                                           : b5;
                #pragma unroll
                for (int pass = 0; pass < 2; ++pass) {
                    const int rr = pass * 12 + (tid >> 4);   // 0..23
                    const int ci2 = rr >> 3, r = rr & 7;
                    const int trow = (ci2 * 5 + slot) * 8 + r;
                    unsigned h0r, h1r, h2r, h3r;
                    if (isf32) {
                        uint4 u0 = *reinterpret_cast<uint4*>(
                            sA + RAW_OFF + rr * 512 + t2 * 32);
                        uint4 u1 = *reinterpret_cast<uint4*>(
                            sA + RAW_OFF + rr * 512 + t2 * 32 + 16);
                        float4 f0 = *reinterpret_cast<float4*>(&u0);
                        float4 f1 = *reinterpret_cast<float4*>(&u1);
                        __half2 a = __floats2half2_rn(f0.x, f0.y);
                        __half2 c = __floats2half2_rn(f0.z, f0.w);
                        __half2 e = __floats2half2_rn(f1.x, f1.y);
                        __half2 g = __floats2half2_rn(f1.z, f1.w);
                        h0r = *reinterpret_cast<unsigned*>(&a);
                        h1r = *reinterpret_cast<unsigned*>(&c);
                        h2r = *reinterpret_cast<unsigned*>(&e);
                        h3r = *reinterpret_cast<unsigned*>(&g);
                    } else {
                        uint4 u = *reinterpret_cast<uint4*>(
                            sA + RAW_OFF + rr * 256 + t2 * 16);
                        h0r = u.x; h1r = u.y; h2r = u.z; h3r = u.w;
                    }
                    sts_shifts(sA, trow, t2, h0r, h1r, h2r, h3r);
                }
            }
            __syncthreads();
        }
    }

    // --- block reduction ---
    #pragma unroll
    for (int o = 16; o >= 1; o >>= 1)
        s += __shfl_xor_sync(0xffffffffu, s, o);
    if (l == 0) swsum[wi] = s;
    __syncthreads();
    if (tid == 0) {
        float tsum = swsum[0] + swsum[1] + swsum[2]
                   + swsum[3] + swsum[4] + swsum[5];
        g_scratch[(b * 3 + hf) * N_HT + ht] = tsum;
    }
}

// ---------------------------------------------------------------------------
__global__ void finalize_kernel(const void* __restrict__ biasr,
                                float* __restrict__ out)
{
    __shared__ float sm[64];
    const int b = blockIdx.x;
    const int tid = threadIdx.x;
    float s = 0.f;
    for (int i = tid; i < 3 * N_HT; i += 64)
        s += g_scratch[b * 3 * N_HT + i];
    sm[tid] = s;
    __syncthreads();
    for (int st = 32; st >= 1; st >>= 1) {
        if (tid < st) sm[tid] += sm[tid + st];
        __syncthreads();
    }
    if (tid == 0) {
        const int isf32 = g_is_f32;
        float bsum = 0.f;
        #pragma unroll
        for (int c = 0; c < 16; ++c)
            bsum += isf32 ? ((const float*)biasr)[c]
                          : __half2float(((const __half*)biasr)[c]);
        // s counts each pooled cell twice -> /2; then /POOL_COUNT; then /2
        out[b] = sm[0] / (4.0f * POOL_COUNT) + bsum;
    }
}

// ---------------------------------------------------------------------------
extern "C" void kernel_launch(void* const* d_in, const int* in_sizes, int n_in,
                              void* d_out, int out_size)
{
    int ix = -1, iw = -1, i16a = -1, i16b = -1;
    for (int i = 0; i < n_in; ++i) {
        if (in_sizes[i] == X_ELEMS) ix = i;
        else if (in_sizes[i] == W_ELEMS) iw = i;
        else if (in_sizes[i] == N_CO) { if (i16a < 0) i16a = i; else i16b = i; }
    }
    int icb, ibias;
    if (ix >= 0 && iw >= 0 && i16a >= 0 && i16b >= 0) {
        int da = (i16a > iw) ? (i16a - iw) : (iw - i16a);
        int db2 = (i16b > iw) ? (i16b - iw) : (iw - i16b);
        if (da <= db2) { icb = i16a; ibias = i16b; }
        else           { icb = i16b; ibias = i16a; }
    } else {
        ix = 0; iw = 1; icb = 2; ibias = 3;
    }

    const void* x  = d_in[ix];
    const void* cw = d_in[iw];
    const void* cb = d_in[icb];
    const void* bs = d_in[ibias];
    float* out = (float*)d_out;

    static int smem_set = 0;
    if (!smem_set) {
        cudaFuncSetAttribute(conv_mma_kernel,
                             cudaFuncAttributeMaxDynamicSharedMemorySize,
                             SMEM_BYTES);
        smem_set = 1;
    }

    prep_kernel<<<1, 256>>>((const unsigned short*)x, cw, cb);
    dim3 grid(N_HT, 3, 32);
    conv_mma_kernel<<<grid, 192, SMEM_BYTES>>>(x);
    finalize_kernel<<<32, 64>>>(bs, out);
}

// round 14
// speedup vs baseline: 1.0075x; 1.0075x over previous
#include <cuda_runtime.h>
#include <cuda_fp16.h>
#include <cstdint>

#define N_HT   21
#define N_UNITS (32 * 3 * N_HT)         // 2016 work units
#define POOL_COUNT 59535.0f             // 15*63*63
#define X_ELEMS  (32*3*32*128*128)
#define W_ELEMS  (16*81)
#define N_CO     16

#define SROWB    272                    // bytes per smem row (136 halfs)
#define ROW3     (3 * SROWB)            // 816
#define SLOTMUL  (8 * ROW3)             // 6528
#define TILE_BYTES (288 * SROWB)        // 78,336
#define STAGE_OFF  TILE_BYTES
#define SMEM_BYTES (TILE_BYTES + 48 * 512)   // 102,912
#define TAIL_T0  (66 * ROW3 + 2 * SROWB)     // k=80 row: ci=2,kh=2,kw=2

__device__ float g_scratch[N_UNITS];
__device__ int   g_is_f32;
__device__ int   g_ctr = 0;             // work counter (reset by finalize)

// ---------------------------------------------------------------------------
#define LDSM4(dst, addr)                                                    \
    asm volatile(                                                           \
        "ldmatrix.sync.aligned.m8n8.x4.trans.shared.b16 {%0,%1,%2,%3}, [%4];" \
        : "=r"((dst)[0]), "=r"((dst)[1]), "=r"((dst)[2]), "=r"((dst)[3])    \
        : "r"(addr))

#define HMMA16(c0, c1, aa, b0, b1)                                          \
    asm volatile(                                                           \
        "mma.sync.aligned.m16n8k16.row.col.f16.f16.f16.f16 "                \
        "{%0,%1}, {%2,%3,%4,%5}, {%6,%7}, {%0,%1};"                         \
        : "+r"(c0), "+r"(c1)                                                \
        : "r"((aa)[0]), "r"((aa)[1]), "r"((aa)[2]), "r"((aa)[3]),           \
          "r"(b0), "r"(b1))

#define CPA16(saddr, gaddr)                                                 \
    asm volatile("cp.async.cg.shared.global [%0], [%1], 16;"                \
                 :: "r"(saddr), "l"(gaddr) : "memory")

__device__ __forceinline__ void sts_shifts(char* sA, int trow, int t2,
                                           unsigned h0r, unsigned h1r,
                                           unsigned h2r, unsigned h3r)
{
    unsigned n0 = __shfl_down_sync(0xffffffffu, h0r, 1);
    if (t2 == 15) n0 = 0u;
    const int base = trow * ROW3 + t2 * 16;
    *reinterpret_cast<uint4*>(sA + base) = make_uint4(h0r, h1r, h2r, h3r);
    unsigned p0 = __byte_perm(h0r, h1r, 0x5432);
    unsigned p1 = __byte_perm(h1r, h2r, 0x5432);
    unsigned p2 = __byte_perm(h2r, h3r, 0x5432);
    unsigned p3 = __byte_perm(h3r, n0,  0x5432);
    *reinterpret_cast<uint4*>(sA + base + SROWB) = make_uint4(p0, p1, p2, p3);
    *reinterpret_cast<uint4*>(sA + base + 2 * SROWB) = make_uint4(h1r, h2r, h3r, n0);
}

__global__ __launch_bounds__(192, 2) void conv_mma_kernel(
    const void* __restrict__ xr,
    const void* __restrict__ cwr,
    const void* __restrict__ cbr)
{
    extern __shared__ __align__(16) char sA[];
    __shared__ float swsum[6];
    __shared__ int s_unit;

    const int tid = threadIdx.x;
    const int wi  = tid >> 5;
    const int l   = tid & 31;

    uint32_t sab;
    asm("{ .reg .u64 t; cvta.to.shared.u64 t, %1; cvt.u32.u64 %0, t; }"
        : "=r"(sab) : "l"(sA));

    // ===== once per block: dtype detect =====
    int bad = 0;
    {
        const unsigned* xw = (const unsigned*)xr;
        unsigned u0 = xw[tid * 2], u1 = xw[tid * 2 + 1];
        #pragma unroll
        for (int sh = 0; sh < 2; ++sh) {
            if ((((u0 >> (sh * 16 + 10)) & 0x1F)) >= 21) bad = 1;
            if ((((u1 >> (sh * 16 + 10)) & 0x1F)) >= 21) bad = 1;
        }
    }
    const int isf32 = __syncthreads_or(bad) ? 1 : 0;
    if (tid == 0) g_is_f32 = isf32;

    // ===== once per block: per-lane B fragments, bias, tail weights =====
    unsigned bfr[20], bias2[2], w81r[2];
    {
        const int q = l & 3;
        const int g = l >> 2;
        #pragma unroll
        for (int ks = 0; ks < 5; ++ks)
            #pragma unroll
            for (int nt = 0; nt < 2; ++nt) {
                const int co = nt * 8 + g;
                __half v[4];
                #pragma unroll
                for (int j = 0; j < 4; ++j) {
                    int k = ks * 16 + 2 * q + ((j >> 1) * 8) + (j & 1); // <80
                    float w = isf32 ? ((const float*)cwr)[co * 81 + k]
                                    : __half2float(((const __half*)cwr)[co * 81 + k]);
                    v[j] = __float2half(w);
                }
                __half2 p0 = __halves2half2(v[0], v[1]);
                __half2 p1 = __halves2half2(v[2], v[3]);
                bfr[ks * 4 + nt * 2 + 0] = *reinterpret_cast<unsigned*>(&p0);
                bfr[ks * 4 + nt * 2 + 1] = *reinterpret_cast<unsigned*>(&p1);
            }
        #pragma unroll
        for (int nt = 0; nt < 2; ++nt) {
            const int c0 = nt * 8 + 2 * q;
            float b0 = isf32 ? ((const float*)cbr)[c0]
                             : __half2float(((const __half*)cbr)[c0]);
            float b1 = isf32 ? ((const float*)cbr)[c0 + 1]
                             : __half2float(((const __half*)cbr)[c0 + 1]);
            __half2 bb = __floats2half2_rn(b0, b1);
            bias2[nt] = *reinterpret_cast<unsigned*>(&bb);
            float w0 = isf32 ? ((const float*)cwr)[c0 * 81 + 80]
                             : __half2float(((const __half*)cwr)[c0 * 81 + 80]);
            float w1 = isf32 ? ((const float*)cwr)[(c0 + 1) * 81 + 80]
                             : __half2float(((const __half*)cwr)[(c0 + 1) * 81 + 80]);
            __half2 ww = __floats2half2_rn(w0, w1);
            w81r[nt] = *reinterpret_cast<unsigned*>(&ww);
        }
    }

    // per-lane k decomposition (k = 0..79, no padding) — unit-invariant
    const int hp    = wi % 3;
    const int mhalf = wi / 3;
    const unsigned klocal = (unsigned)((l & 7) | ((l & 16) >> 1));
    const unsigned wbyte  = (unsigned)((l & 8) << 1);
    const unsigned m0b    = (unsigned)(mhalf * 128);
    unsigned rowbase[5];
    int kdv[5];
    #pragma unroll
    for (int ks = 0; ks < 5; ++ks) {
        const int k = ks * 16 + (int)klocal;
        int ci = k / 27;  int rm = k - ci * 27;
        int kd = rm / 9;  rm -= kd * 9;
        int kh = rm / 3;  int kw = rm - kh * 3;
        rowbase[ks] = (unsigned)((ci * 32 + kh) * ROW3 + kw * SROWB);
        kdv[ks] = kd;
    }
    const __half2 z2 = __float2half2_rn(0.f);
    const bool v23ok = !(mhalf == 1 && (l >> 2) >= 6);
    const int t2 = l & 15;

    // ===== persistent work-stealing loop =====
    for (;;) {
        if (tid == 0) s_unit = atomicAdd(&g_ctr, 1);
        __syncthreads();
        const int unit = s_unit;
        if (unit >= N_UNITS) break;

        const int ht = unit % N_HT;
        const int r2 = unit / N_HT;
        const int hf = r2 % 3;
        const int b  = r2 / 3;
        const int db = hf * 10;
        const int h0 = ht * 6;

        // --- prologue: stage depths db..db+3 into slots 0..3, batched ---
        if (isf32) {
            uint4 raw[8][2];
            #pragma unroll
            for (int it = 0; it < 8; ++it) {
                const int row = wi * 16 + it * 2 + (l >> 4);
                const int ci = row >> 5, dzi = (row >> 3) & 3, rr = row & 7;
                const long goff =
                    ((long)((b * 3 + ci) * 32 + db + dzi) * 128 + (h0 + rr)) * 128 + t2 * 8;
                const uint4* gp = reinterpret_cast<const uint4*>((const float*)xr + goff);
                raw[it][0] = gp[0];
                raw[it][1] = gp[1];
            }
            #pragma unroll
            for (int it = 0; it < 8; ++it) {
                const int row = wi * 16 + it * 2 + (l >> 4);
                const int ci = row >> 5, dzi = (row >> 3) & 3, rr = row & 7;
                const int trow = (ci * 4 + ((db + dzi) & 3)) * 8 + rr;
                float4 f0 = *reinterpret_cast<float4*>(&raw[it][0]);
                float4 f1 = *reinterpret_cast<float4*>(&raw[it][1]);
                __half2 a = __floats2half2_rn(f0.x, f0.y);
                __half2 c = __floats2half2_rn(f0.z, f0.w);
                __half2 e = __floats2half2_rn(f1.x, f1.y);
                __half2 g = __floats2half2_rn(f1.z, f1.w);
                sts_shifts(sA, trow, t2,
                           *reinterpret_cast<unsigned*>(&a),
                           *reinterpret_cast<unsigned*>(&c),
                           *reinterpret_cast<unsigned*>(&e),
                           *reinterpret_cast<unsigned*>(&g));
            }
        } else {
            uint4 raw[8];
            #pragma unroll
            for (int it = 0; it < 8; ++it) {
                const int row = wi * 16 + it * 2 + (l >> 4);
                const int ci = row >> 5, dzi = (row >> 3) & 3, rr = row & 7;
                const long goff =
                    ((long)((b * 3 + ci) * 32 + db + dzi) * 128 + (h0 + rr)) * 128 + t2 * 8;
                raw[it] = *reinterpret_cast<const uint4*>((const __half*)xr + goff);
            }
            #pragma unroll
            for (int it = 0; it < 8; ++it) {
                const int row = wi * 16 + it * 2 + (l >> 4);
                const int ci = row >> 5, dzi = (row >> 3) & 3, rr = row & 7;
                const int trow = (ci * 4 + ((db + dzi) & 3)) * 8 + rr;
                sts_shifts(sA, trow, t2, raw[it].x, raw[it].y, raw[it].z, raw[it].w);
            }
        }
        __syncthreads();

        float s = 0.f;
        unsigned pm01[4][2], pm23[4][2];
        #pragma unroll
        for (int mt = 0; mt < 4; ++mt)
            #pragma unroll
            for (int nt = 0; nt < 2; ++nt) { pm01[mt][nt] = 0u; pm23[mt][nt] = 0u; }

        // ---- depth-rolling main loop (4-slot ring, proven R11 body) ----
        #pragma unroll 1
        for (int dpi = 0; dpi < 5; ++dpi) {
            const bool nxt = (dpi + 1 < 5);
            const int dnew0 = db + 2 * dpi + 4;

            if (nxt) {
                if (isf32) {
                    #pragma unroll
                    for (int p = 0; p < 8; ++p) {
                        const int c  = tid + p * 192;
                        const int rr = c >> 5;
                        const int ch = c & 31;
                        const int ci = rr >> 4, dzi = (rr >> 3) & 1, rx = rr & 7;
                        const char* g = (const char*)xr +
                            (((long)((b * 3 + ci) * 32 + dnew0 + dzi) * 128
                              + (h0 + rx)) * 128) * 4 + ch * 16;
                        CPA16(sab + STAGE_OFF + rr * 512 + ch * 16, g);
                    }
                } else {
                    #pragma unroll
                    for (int p = 0; p < 4; ++p) {
                        const int c  = tid + p * 192;
                        const int rr = c >> 4;
                        const int ch = c & 15;
                        const int ci = rr >> 4, dzi = (rr >> 3) & 1, rx = rr & 7;
                        const char* g = (const char*)xr +
                            (((long)((b * 3 + ci) * 32 + dnew0 + dzi) * 128
                              + (h0 + rx)) * 128) * 2 + ch * 16;
                        CPA16(sab + STAGE_OFF + rr * 256 + ch * 16, g);
                    }
                }
                asm volatile("cp.async.commit_group;" ::: "memory");
            }

            const int base0 = (db + 2 * dpi) & 3;
            unsigned rowb_dd[2][5];
            unsigned tailoff[2];
            #pragma unroll
            for (int dd = 0; dd < 2; ++dd) {
                #pragma unroll
                for (int ks = 0; ks < 5; ++ks)
                    rowb_dd[dd][ks] = rowbase[ks]
                        + (unsigned)(((base0 + dd + kdv[ks]) & 3) * SLOTMUL);
                tailoff[dd] = (unsigned)TAIL_T0
                            + (unsigned)(((base0 + dd + 2) & 3) * SLOTMUL);
            }

            #pragma unroll
            for (int dd = 0; dd < 2; ++dd) {
                #pragma unroll 1
                for (int h2 = 0; h2 < 2; ++h2) {
                    const int hh = hp * 2 + h2;
                    const unsigned abase = sab + (unsigned)(hh * ROW3) + wbyte + m0b;
                    unsigned c01[4][2], c23[4][2];
                    #pragma unroll
                    for (int mt = 0; mt < 4; ++mt)
                        #pragma unroll
                        for (int nt = 0; nt < 2; ++nt) { c01[mt][nt] = 0u; c23[mt][nt] = 0u; }

                    unsigned afr[2][4][4];
                    #pragma unroll
                    for (int mt = 0; mt < 4; ++mt)
                        LDSM4(afr[0][mt], abase + rowb_dd[dd][0] + mt * 32);

                    #pragma unroll
                    for (int ks = 0; ks < 5; ++ks) {
                        const int cur = ks & 1;
                        if (ks < 4) {
                            #pragma unroll
                            for (int mt = 0; mt < 4; ++mt)
                                LDSM4(afr[cur ^ 1][mt], abase + rowb_dd[dd][ks + 1] + mt * 32);
                        }
                        const unsigned b0 = bfr[ks * 4 + 0];
                        const unsigned b1 = bfr[ks * 4 + 1];
                        const unsigned b2 = bfr[ks * 4 + 2];
                        const unsigned b3 = bfr[ks * 4 + 3];
                        #pragma unroll
                        for (int mt = 0; mt < 4; ++mt) {
                            HMMA16(c01[mt][0], c23[mt][0], afr[cur][mt], b0, b1);
                            HMMA16(c01[mt][1], c23[mt][1], afr[cur][mt], b2, b3);
                        }
                    }

                    // tail tap k=80: rank-1 update
                    {
                        const int toff = (int)tailoff[dd] + hh * ROW3
                                       + (int)m0b + ((l >> 2) << 1);
                        #pragma unroll
                        for (int mt = 0; mt < 4; ++mt) {
                            __half x0 = *reinterpret_cast<const __half*>(
                                sA + toff + mt * 32);
                            __half x1 = *reinterpret_cast<const __half*>(
                                sA + toff + mt * 32 + 16);
                            __half2 x00 = __half2half2(x0);
                            __half2 x11 = __half2half2(x1);
                            #pragma unroll
                            for (int nt = 0; nt < 2; ++nt) {
                                __half2 ww = *reinterpret_cast<__half2*>(&w81r[nt]);
                                __half2 cc0 = *reinterpret_cast<__half2*>(&c01[mt][nt]);
                                __half2 cc1 = *reinterpret_cast<__half2*>(&c23[mt][nt]);
                                cc0 = __hfma2(x00, ww, cc0);
                                cc1 = __hfma2(x11, ww, cc1);
                                c01[mt][nt] = *reinterpret_cast<unsigned*>(&cc0);
                                c23[mt][nt] = *reinterpret_cast<unsigned*>(&cc1);
                            }
                        }
                    }

                    // +bias, relu, fold into pooled max
                    #pragma unroll
                    for (int mt = 0; mt < 4; ++mt)
                        #pragma unroll
                        for (int nt = 0; nt < 2; ++nt) {
                            __half2 bb = *reinterpret_cast<__half2*>(&bias2[nt]);
                            __half2 h01 = __hmax2(__hadd2(
                                *reinterpret_cast<__half2*>(&c01[mt][nt]), bb), z2);
                            __half2 h23 = __hmax2(__hadd2(
                                *reinterpret_cast<__half2*>(&c23[mt][nt]), bb), z2);
                            __half2 p0 = *reinterpret_cast<__half2*>(&pm01[mt][nt]);
                            __half2 p1 = *reinterpret_cast<__half2*>(&pm23[mt][nt]);
                            p0 = __hmax2(p0, h01);
                            p1 = __hmax2(p1, h23);
                            pm01[mt][nt] = *reinterpret_cast<unsigned*>(&p0);
                            pm23[mt][nt] = *reinterpret_cast<unsigned*>(&p1);
                        }
                }
            }

            // per-dp pooling extract
            #pragma unroll
            for (int mt = 0; mt < 4; ++mt)
                #pragma unroll
                for (int nt = 0; nt < 2; ++nt) {
                    unsigned q01 = pm01[mt][nt];
                    unsigned o01 = __shfl_xor_sync(0xffffffffu, q01, 4);
                    __half2 m01 = __hmax2(*reinterpret_cast<__half2*>(&q01),
                                          *reinterpret_cast<__half2*>(&o01));
                    float2 f01 = __half22float2(m01);
                    s += f01.x + f01.y;

                    unsigned q23 = pm23[mt][nt];
                    unsigned o23 = __shfl_xor_sync(0xffffffffu, q23, 4);
                    __half2 m23 = __hmax2(*reinterpret_cast<__half2*>(&q23),
                                          *reinterpret_cast<__half2*>(&o23));
                    if (mt != 3 || v23ok) {
                        float2 f23 = __half22float2(m23);
                        s += f23.x + f23.y;
                    }
                    pm01[mt][nt] = 0u;
                    pm23[mt][nt] = 0u;
                }

            // drain prefetch, convert raw -> tile
            if (nxt) {
                asm volatile("cp.async.wait_group 0;" ::: "memory");
                __syncthreads();
                #pragma unroll
                for (int p = 0; p < 4; ++p) {
                    const int rr = p * 12 + (tid >> 4);
                    const int ci = rr >> 4, dzi = (rr >> 3) & 1, rx = rr & 7;
                    const int slot = (dnew0 + dzi) & 3;
                    const int trow = (ci * 4 + slot) * 8 + rx;
                    unsigned h0r, h1r, h2r, h3r;
                    if (isf32) {
                        uint4 u0 = *reinterpret_cast<uint4*>(sA + STAGE_OFF + rr * 512 + t2 * 32);
                        uint4 u1 = *reinterpret_cast<uint4*>(sA + STAGE_OFF + rr * 512 + t2 * 32 + 16);
                        float4 f0 = *reinterpret_cast<float4*>(&u0);
                        float4 f1 = *reinterpret_cast<float4*>(&u1);
                        __half2 a = __floats2half2_rn(f0.x, f0.y);
                        __half2 c = __floats2half2_rn(f0.z, f0.w);
                        __half2 e = __floats2half2_rn(f1.x, f1.y);
                        __half2 g = __floats2half2_rn(f1.z, f1.w);
                        h0r = *reinterpret_cast<unsigned*>(&a);
                        h1r = *reinterpret_cast<unsigned*>(&c);
                        h2r = *reinterpret_cast<unsigned*>(&e);
                        h3r = *reinterpret_cast<unsigned*>(&g);
                    } else {
                        uint4 u = *reinterpret_cast<uint4*>(sA + STAGE_OFF + rr * 256 + t2 * 16);
                        h0r = u.x; h1r = u.y; h2r = u.z; h3r = u.w;
                    }
                    sts_shifts(sA, trow, t2, h0r, h1r, h2r, h3r);
                }
                __syncthreads();
            }
        }

        // --- block reduction for this unit ---
        #pragma unroll
        for (int o = 16; o >= 1; o >>= 1)
            s += __shfl_xor_sync(0xffffffffu, s, o);
        if (l == 0) swsum[wi] = s;
        __syncthreads();
        if (tid == 0) {
            g_scratch[unit] = swsum[0] + swsum[1] + swsum[2]
                            + swsum[3] + swsum[4] + swsum[5];
        }
        __syncthreads();   // protect swsum/s_unit before next iteration
    }
}

// ---------------------------------------------------------------------------
__global__ void finalize_kernel(const void* __restrict__ biasr,
                                float* __restrict__ out)
{
    __shared__ float sm[64];
    const int b = blockIdx.x;
    const int tid = threadIdx.x;
    if (b == 0 && tid == 0) g_ctr = 0;   // reset work counter for next replay
    float s = 0.f;
    for (int i = tid; i < 3 * N_HT; i += 64)
        s += g_scratch[b * 3 * N_HT + i];
    sm[tid] = s;
    __syncthreads();
    for (int st = 32; st >= 1; st >>= 1) {
        if (tid < st) sm[tid] += sm[tid + st];
        __syncthreads();
    }
    if (tid == 0) {
        const int isf32 = g_is_f32;
        float bsum = 0.f;
        #pragma unroll
        for (int c = 0; c < 16; ++c)
            bsum += isf32 ? ((const float*)biasr)[c]
                          : __half2float(((const __half*)biasr)[c]);
        // s counts each pooled cell twice -> /2; then /POOL_COUNT; then /2
        out[b] = sm[0] / (4.0f * POOL_COUNT) + bsum;
    }
}

// ---------------------------------------------------------------------------
extern "C" void kernel_launch(void* const* d_in, const int* in_sizes, int n_in,
                              void* d_out, int out_size)
{
    int ix = -1, iw = -1, i16a = -1, i16b = -1;
    for (int i = 0; i < n_in; ++i) {
        if (in_sizes[i] == X_ELEMS) ix = i;
        else if (in_sizes[i] == W_ELEMS) iw = i;
        else if (in_sizes[i] == N_CO) { if (i16a < 0) i16a = i; else i16b = i; }
    }
    int icb, ibias;
    if (ix >= 0 && iw >= 0 && i16a >= 0 && i16b >= 0) {
        int da = (i16a > iw) ? (i16a - iw) : (iw - i16a);
        int db2 = (i16b > iw) ? (i16b - iw) : (iw - i16b);
        if (da <= db2) { icb = i16a; ibias = i16b; }
        else           { icb = i16b; ibias = i16a; }
    } else {
        ix = 0; iw = 1; icb = 2; ibias = 3;
    }

    const void* x  = d_in[ix];
    const void* cw = d_in[iw];
    const void* cb = d_in[icb];
    const void* bs = d_in[ibias];
    float* out = (float*)d_out;

    static int smem_set = 0;
    if (!smem_set) {
        cudaFuncSetAttribute(conv_mma_kernel,
                             cudaFuncAttributeMaxDynamicSharedMemorySize,
                             SMEM_BYTES);
        smem_set = 1;
    }

    conv_mma_kernel<<<304, 192, SMEM_BYTES>>>(x, cw, cb);
    finalize_kernel<<<32, 64>>>(bs, out);
}

// round 15
// speedup vs baseline: 1.0230x; 1.0154x over previous
#include <cuda_runtime.h>
#include <cuda_fp16.h>
#include <cstdint>

#define N_HT   21
#define N_UNITS (32 * 3 * N_HT)         // 2016 work units
#define POOL_COUNT 59535.0f             // 15*63*63
#define X_ELEMS  (32*3*32*128*128)
#define W_ELEMS  (16*81)
#define N_CO     16

#define SROWB    272                    // bytes per smem row (136 halfs)
#define ROW3     (3 * SROWB)            // 816
#define SLOTMUL  (8 * ROW3)             // 6528
#define TILE_BYTES (288 * SROWB)        // 78,336
#define STAGE_OFF  TILE_BYTES
#define SMEM_BYTES (TILE_BYTES + 48 * 512)   // 102,912
#define TAIL_T0  (66 * ROW3 + 2 * SROWB)     // k=80 row: ci=2,kh=2,kw=2

__device__ float g_scratch[N_UNITS];
__device__ int   g_is_f32;
__device__ int   g_ctr = 0;             // work counter (reset by finalize)

// ---------------------------------------------------------------------------
#define LDSM4(dst, addr)                                                    \
    asm volatile(                                                           \
        "ldmatrix.sync.aligned.m8n8.x4.trans.shared.b16 {%0,%1,%2,%3}, [%4];" \
        : "=r"((dst)[0]), "=r"((dst)[1]), "=r"((dst)[2]), "=r"((dst)[3])    \
        : "r"(addr))

// NOTE: NOT volatile — pure register op, lets ptxas interleave freely.
#define HMMA16(c0, c1, aa, b0, b1)                                          \
    asm("mma.sync.aligned.m16n8k16.row.col.f16.f16.f16.f16 "                \
        "{%0,%1}, {%2,%3,%4,%5}, {%6,%7}, {%0,%1};"                         \
        : "+r"(c0), "+r"(c1)                                                \
        : "r"((aa)[0]), "r"((aa)[1]), "r"((aa)[2]), "r"((aa)[3]),           \
          "r"(b0), "r"(b1))

#define CPA16(saddr, gaddr)                                                 \
    asm volatile("cp.async.cg.shared.global [%0], [%1], 16;"                \
                 :: "r"(saddr), "l"(gaddr) : "memory")

__device__ __forceinline__ void sts_shifts(char* sA, int trow, int t2,
                                           unsigned h0r, unsigned h1r,
                                           unsigned h2r, unsigned h3r)
{
    unsigned n0 = __shfl_down_sync(0xffffffffu, h0r, 1);
    if (t2 == 15) n0 = 0u;
    const int base = trow * ROW3 + t2 * 16;
    *reinterpret_cast<uint4*>(sA + base) = make_uint4(h0r, h1r, h2r, h3r);
    unsigned p0 = __byte_perm(h0r, h1r, 0x5432);
    unsigned p1 = __byte_perm(h1r, h2r, 0x5432);
    unsigned p2 = __byte_perm(h2r, h3r, 0x5432);
    unsigned p3 = __byte_perm(h3r, n0,  0x5432);
    *reinterpret_cast<uint4*>(sA + base + SROWB) = make_uint4(p0, p1, p2, p3);
    *reinterpret_cast<uint4*>(sA + base + 2 * SROWB) = make_uint4(h1r, h2r, h3r, n0);
}

__global__ __launch_bounds__(192, 2) void conv_mma_kernel(
    const void* __restrict__ xr,
    const void* __restrict__ cwr,
    const void* __restrict__ cbr)
{
    extern __shared__ __align__(16) char sA[];
    __shared__ float swsum[6];
    __shared__ int s_unit;

    const int tid = threadIdx.x;
    const int wi  = tid >> 5;
    const int l   = tid & 31;

    uint32_t sab;
    asm("{ .reg .u64 t; cvta.to.shared.u64 t, %1; cvt.u32.u64 %0, t; }"
        : "=r"(sab) : "l"(sA));

    // ===== once per block: dtype detect =====
    int bad = 0;
    {
        const unsigned* xw = (const unsigned*)xr;
        unsigned u0 = xw[tid * 2], u1 = xw[tid * 2 + 1];
        #pragma unroll
        for (int sh = 0; sh < 2; ++sh) {
            if ((((u0 >> (sh * 16 + 10)) & 0x1F)) >= 21) bad = 1;
            if ((((u1 >> (sh * 16 + 10)) & 0x1F)) >= 21) bad = 1;
        }
    }
    const int isf32 = __syncthreads_or(bad) ? 1 : 0;
    if (tid == 0) g_is_f32 = isf32;

    // ===== once per block: per-lane B fragments, bias, tail weights =====
    unsigned bfr[20], bias2[2], w81r[2];
    {
        const int q = l & 3;
        const int g = l >> 2;
        #pragma unroll
        for (int ks = 0; ks < 5; ++ks)
            #pragma unroll
            for (int nt = 0; nt < 2; ++nt) {
                const int co = nt * 8 + g;
                __half v[4];
                #pragma unroll
                for (int j = 0; j < 4; ++j) {
                    int k = ks * 16 + 2 * q + ((j >> 1) * 8) + (j & 1); // <80
                    float w = isf32 ? ((const float*)cwr)[co * 81 + k]
                                    : __half2float(((const __half*)cwr)[co * 81 + k]);
                    v[j] = __float2half(w);
                }
                __half2 p0 = __halves2half2(v[0], v[1]);
                __half2 p1 = __halves2half2(v[2], v[3]);
                bfr[ks * 4 + nt * 2 + 0] = *reinterpret_cast<unsigned*>(&p0);
                bfr[ks * 4 + nt * 2 + 1] = *reinterpret_cast<unsigned*>(&p1);
            }
        #pragma unroll
        for (int nt = 0; nt < 2; ++nt) {
            const int c0 = nt * 8 + 2 * q;
            float b0 = isf32 ? ((const float*)cbr)[c0]
                             : __half2float(((const __half*)cbr)[c0]);
            float b1 = isf32 ? ((const float*)cbr)[c0 + 1]
                             : __half2float(((const __half*)cbr)[c0 + 1]);
            __half2 bb = __floats2half2_rn(b0, b1);
            bias2[nt] = *reinterpret_cast<unsigned*>(&bb);
            float w0 = isf32 ? ((const float*)cwr)[c0 * 81 + 80]
                             : __half2float(((const __half*)cwr)[c0 * 81 + 80]);
            float w1 = isf32 ? ((const float*)cwr)[(c0 + 1) * 81 + 80]
                             : __half2float(((const __half*)cwr)[(c0 + 1) * 81 + 80]);
            __half2 ww = __floats2half2_rn(w0, w1);
            w81r[nt] = *reinterpret_cast<unsigned*>(&ww);
        }
    }

    // per-lane k decomposition (k = 0..79, no padding) — unit-invariant
    const int hp    = wi % 3;
    const int mhalf = wi / 3;
    const unsigned klocal = (unsigned)((l & 7) | ((l & 16) >> 1));
    const unsigned wbyte  = (unsigned)((l & 8) << 1);
    const unsigned m0b    = (unsigned)(mhalf * 128);
    unsigned rowbase[5];
    int kdv[5];
    #pragma unroll
    for (int ks = 0; ks < 5; ++ks) {
        const int k = ks * 16 + (int)klocal;
        int ci = k / 27;  int rm = k - ci * 27;
        int kd = rm / 9;  rm -= kd * 9;
        int kh = rm / 3;  int kw = rm - kh * 3;
        rowbase[ks] = (unsigned)((ci * 32 + kh) * ROW3 + kw * SROWB);
        kdv[ks] = kd;
    }
    const __half2 z2 = __float2half2_rn(0.f);
    const bool v23ok = !(mhalf == 1 && (l >> 2) >= 6);
    const int t2 = l & 15;

    // ===== persistent work-stealing loop =====
    for (;;) {
        if (tid == 0) s_unit = atomicAdd(&g_ctr, 1);
        __syncthreads();
        const int unit = s_unit;
        if (unit >= N_UNITS) break;

        const int ht = unit % N_HT;
        const int r2 = unit / N_HT;
        const int hf = r2 % 3;
        const int b  = r2 / 3;
        const int db = hf * 10;
        const int h0 = ht * 6;

        // --- prologue: stage depths db..db+3 into slots 0..3, batched ---
        if (isf32) {
            uint4 raw[8][2];
            #pragma unroll
            for (int it = 0; it < 8; ++it) {
                const int row = wi * 16 + it * 2 + (l >> 4);
                const int ci = row >> 5, dzi = (row >> 3) & 3, rr = row & 7;
                const long goff =
                    ((long)((b * 3 + ci) * 32 + db + dzi) * 128 + (h0 + rr)) * 128 + t2 * 8;
                const uint4* gp = reinterpret_cast<const uint4*>((const float*)xr + goff);
                raw[it][0] = gp[0];
                raw[it][1] = gp[1];
            }
            #pragma unroll
            for (int it = 0; it < 8; ++it) {
                const int row = wi * 16 + it * 2 + (l >> 4);
                const int ci = row >> 5, dzi = (row >> 3) & 3, rr = row & 7;
                const int trow = (ci * 4 + ((db + dzi) & 3)) * 8 + rr;
                float4 f0 = *reinterpret_cast<float4*>(&raw[it][0]);
                float4 f1 = *reinterpret_cast<float4*>(&raw[it][1]);
                __half2 a = __floats2half2_rn(f0.x, f0.y);
                __half2 c = __floats2half2_rn(f0.z, f0.w);
                __half2 e = __floats2half2_rn(f1.x, f1.y);
                __half2 g = __floats2half2_rn(f1.z, f1.w);
                sts_shifts(sA, trow, t2,
                           *reinterpret_cast<unsigned*>(&a),
                           *reinterpret_cast<unsigned*>(&c),
                           *reinterpret_cast<unsigned*>(&e),
                           *reinterpret_cast<unsigned*>(&g));
            }
        } else {
            uint4 raw[8];
            #pragma unroll
            for (int it = 0; it < 8; ++it) {
                const int row = wi * 16 + it * 2 + (l >> 4);
                const int ci = row >> 5, dzi = (row >> 3) & 3, rr = row & 7;
                const long goff =
                    ((long)((b * 3 + ci) * 32 + db + dzi) * 128 + (h0 + rr)) * 128 + t2 * 8;
                raw[it] = *reinterpret_cast<const uint4*>((const __half*)xr + goff);
            }
            #pragma unroll
            for (int it = 0; it < 8; ++it) {
                const int row = wi * 16 + it * 2 + (l >> 4);
                const int ci = row >> 5, dzi = (row >> 3) & 3, rr = row & 7;
                const int trow = (ci * 4 + ((db + dzi) & 3)) * 8 + rr;
                sts_shifts(sA, trow, t2, raw[it].x, raw[it].y, raw[it].z, raw[it].w);
            }
        }
        __syncthreads();

        float s = 0.f;
        unsigned pm01[4][2], pm23[4][2];
        #pragma unroll
        for (int mt = 0; mt < 4; ++mt)
            #pragma unroll
            for (int nt = 0; nt < 2; ++nt) { pm01[mt][nt] = 0u; pm23[mt][nt] = 0u; }

        // ---- depth-rolling main loop (4-slot ring) ----
        #pragma unroll 1
        for (int dpi = 0; dpi < 5; ++dpi) {
            const bool nxt = (dpi + 1 < 5);
            const int dnew0 = db + 2 * dpi + 4;

            if (nxt) {
                if (isf32) {
                    #pragma unroll
                    for (int p = 0; p < 8; ++p) {
                        const int c  = tid + p * 192;
                        const int rr = c >> 5;
                        const int ch = c & 31;
                        const int ci = rr >> 4, dzi = (rr >> 3) & 1, rx = rr & 7;
                        const char* g = (const char*)xr +
                            (((long)((b * 3 + ci) * 32 + dnew0 + dzi) * 128
                              + (h0 + rx)) * 128) * 4 + ch * 16;
                        CPA16(sab + STAGE_OFF + rr * 512 + ch * 16, g);
                    }
                } else {
                    #pragma unroll
                    for (int p = 0; p < 4; ++p) {
                        const int c  = tid + p * 192;
                        const int rr = c >> 4;
                        const int ch = c & 15;
                        const int ci = rr >> 4, dzi = (rr >> 3) & 1, rx = rr & 7;
                        const char* g = (const char*)xr +
                            (((long)((b * 3 + ci) * 32 + dnew0 + dzi) * 128
                              + (h0 + rx)) * 128) * 2 + ch * 16;
                        CPA16(sab + STAGE_OFF + rr * 256 + ch * 16, g);
                    }
                }
                asm volatile("cp.async.commit_group;" ::: "memory");
            }

            const int base0 = (db + 2 * dpi) & 3;
            unsigned rowb_dd[2][5];
            unsigned tailoff[2];
            #pragma unroll
            for (int dd = 0; dd < 2; ++dd) {
                #pragma unroll
                for (int ks = 0; ks < 5; ++ks)
                    rowb_dd[dd][ks] = rowbase[ks]
                        + (unsigned)(((base0 + dd + kdv[ks]) & 3) * SLOTMUL);
                tailoff[dd] = (unsigned)TAIL_T0
                            + (unsigned)(((base0 + dd + 2) & 3) * SLOTMUL);
            }

            // ---- 4 GEMM phases fully unrolled (straight-line block):
            //      non-volatile HMMAs + deferred-schedulable epilogues let
            //      ptxas interleave epilogue ALU into tensor stall slots ----
            #pragma unroll
            for (int ph = 0; ph < 4; ++ph) {
                const int dd = ph >> 1;
                const int h2 = ph & 1;
                const int hh = hp * 2 + h2;
                const unsigned abase = sab + (unsigned)(hh * ROW3) + wbyte + m0b;

                // tail-tap x loads hoisted to phase start (independent of C)
                __half2 x00[4], x11[4];
                {
                    const int toff = (int)tailoff[dd] + hh * ROW3
                                   + (int)m0b + ((l >> 2) << 1);
                    #pragma unroll
                    for (int mt = 0; mt < 4; ++mt) {
                        __half x0 = *reinterpret_cast<const __half*>(
                            sA + toff + mt * 32);
                        __half x1 = *reinterpret_cast<const __half*>(
                            sA + toff + mt * 32 + 16);
                        x00[mt] = __half2half2(x0);
                        x11[mt] = __half2half2(x1);
                    }
                }

                unsigned c01[4][2], c23[4][2];
                #pragma unroll
                for (int mt = 0; mt < 4; ++mt)
                    #pragma unroll
                    for (int nt = 0; nt < 2; ++nt) { c01[mt][nt] = 0u; c23[mt][nt] = 0u; }

                unsigned afr[2][4][4];
                #pragma unroll
                for (int mt = 0; mt < 4; ++mt)
                    LDSM4(afr[0][mt], abase + rowb_dd[dd][0] + mt * 32);

                #pragma unroll
                for (int ks = 0; ks < 5; ++ks) {
                    const int cur = ks & 1;
                    if (ks < 4) {
                        #pragma unroll
                        for (int mt = 0; mt < 4; ++mt)
                            LDSM4(afr[cur ^ 1][mt], abase + rowb_dd[dd][ks + 1] + mt * 32);
                    }
                    const unsigned b0 = bfr[ks * 4 + 0];
                    const unsigned b1 = bfr[ks * 4 + 1];
                    const unsigned b2 = bfr[ks * 4 + 2];
                    const unsigned b3 = bfr[ks * 4 + 3];
                    #pragma unroll
                    for (int mt = 0; mt < 4; ++mt) {
                        HMMA16(c01[mt][0], c23[mt][0], afr[cur][mt], b0, b1);
                        HMMA16(c01[mt][1], c23[mt][1], afr[cur][mt], b2, b3);
                    }
                }

                // tail tap k=80 (x preloaded), +bias, relu, fold into max
                #pragma unroll
                for (int mt = 0; mt < 4; ++mt)
                    #pragma unroll
                    for (int nt = 0; nt < 2; ++nt) {
                        __half2 ww = *reinterpret_cast<__half2*>(&w81r[nt]);
                        __half2 bb = *reinterpret_cast<__half2*>(&bias2[nt]);
                        __half2 cc0 = *reinterpret_cast<__half2*>(&c01[mt][nt]);
                        __half2 cc1 = *reinterpret_cast<__half2*>(&c23[mt][nt]);
                        cc0 = __hfma2(x00[mt], ww, cc0);
                        cc1 = __hfma2(x11[mt], ww, cc1);
                        __half2 h01 = __hmax2(__hadd2(cc0, bb), z2);
                        __half2 h23 = __hmax2(__hadd2(cc1, bb), z2);
                        __half2 p0 = *reinterpret_cast<__half2*>(&pm01[mt][nt]);
                        __half2 p1 = *reinterpret_cast<__half2*>(&pm23[mt][nt]);
                        p0 = __hmax2(p0, h01);
                        p1 = __hmax2(p1, h23);
                        pm01[mt][nt] = *reinterpret_cast<unsigned*>(&p0);
                        pm23[mt][nt] = *reinterpret_cast<unsigned*>(&p1);
                    }
            }

            // per-dp pooling extract
            #pragma unroll
            for (int mt = 0; mt < 4; ++mt)
                #pragma unroll
                for (int nt = 0; nt < 2; ++nt) {
                    unsigned q01 = pm01[mt][nt];
                    unsigned o01 = __shfl_xor_sync(0xffffffffu, q01, 4);
                    __half2 m01 = __hmax2(*reinterpret_cast<__half2*>(&q01),
                                          *reinterpret_cast<__half2*>(&o01));
                    float2 f01 = __half22float2(m01);
                    s += f01.x + f01.y;

                    unsigned q23 = pm23[mt][nt];
                    unsigned o23 = __shfl_xor_sync(0xffffffffu, q23, 4);
                    __half2 m23 = __hmax2(*reinterpret_cast<__half2*>(&q23),
                                          *reinterpret_cast<__half2*>(&o23));
                    if (mt != 3 || v23ok) {
                        float2 f23 = __half22float2(m23);
                        s += f23.x + f23.y;
                    }
                    pm01[mt][nt] = 0u;
                    pm23[mt][nt] = 0u;
                }

            // drain prefetch, convert raw -> tile
            if (nxt) {
                asm volatile("cp.async.wait_group 0;" ::: "memory");
                __syncthreads();
                #pragma unroll
                for (int p = 0; p < 4; ++p) {
                    const int rr = p * 12 + (tid >> 4);
                    const int ci = rr >> 4, dzi = (rr >> 3) & 1, rx = rr & 7;
                    const int slot = (dnew0 + dzi) & 3;
                    const int trow = (ci * 4 + slot) * 8 + rx;
                    unsigned h0r, h1r, h2r, h3r;
                    if (isf32) {
                        uint4 u0 = *reinterpret_cast<uint4*>(sA + STAGE_OFF + rr * 512 + t2 * 32);
                        uint4 u1 = *reinterpret_cast<uint4*>(sA + STAGE_OFF + rr * 512 + t2 * 32 + 16);
                        float4 f0 = *reinterpret_cast<float4*>(&u0);
                        float4 f1 = *reinterpret_cast<float4*>(&u1);
                        __half2 a = __floats2half2_rn(f0.x, f0.y);
                        __half2 c = __floats2half2_rn(f0.z, f0.w);
                        __half2 e = __floats2half2_rn(f1.x, f1.y);
                        __half2 g = __floats2half2_rn(f1.z, f1.w);
                        h0r = *reinterpret_cast<unsigned*>(&a);
                        h1r = *reinterpret_cast<unsigned*>(&c);
                        h2r = *reinterpret_cast<unsigned*>(&e);
                        h3r = *reinterpret_cast<unsigned*>(&g);
                    } else {
                        uint4 u = *reinterpret_cast<uint4*>(sA + STAGE_OFF + rr * 256 + t2 * 16);
                        h0r = u.x; h1r = u.y; h2r = u.z; h3r = u.w;
                    }
                    sts_shifts(sA, trow, t2, h0r, h1r, h2r, h3r);
                }
                __syncthreads();
            }
        }

        // --- block reduction for this unit ---
        #pragma unroll
        for (int o = 16; o >= 1; o >>= 1)
            s += __shfl_xor_sync(0xffffffffu, s, o);
        if (l == 0) swsum[wi] = s;
        __syncthreads();
        if (tid == 0) {
            g_scratch[unit] = swsum[0] + swsum[1] + swsum[2]
                            + swsum[3] + swsum[4] + swsum[5];
        }
        __syncthreads();   // protect swsum/s_unit before next iteration
    }
}

// ---------------------------------------------------------------------------
__global__ void finalize_kernel(const void* __restrict__ biasr,
                                float* __restrict__ out)
{
    __shared__ float sm[64];
    const int b = blockIdx.x;
    const int tid = threadIdx.x;
    if (b == 0 && tid == 0) g_ctr = 0;   // reset work counter for next replay
    float s = 0.f;
    for (int i = tid; i < 3 * N_HT; i += 64)
        s += g_scratch[b * 3 * N_HT + i];
    sm[tid] = s;
    __syncthreads();
    for (int st = 32; st >= 1; st >>= 1) {
        if (tid < st) sm[tid] += sm[tid + st];
        __syncthreads();
    }
    if (tid == 0) {
        const int isf32 = g_is_f32;
        float bsum = 0.f;
        #pragma unroll
        for (int c = 0; c < 16; ++c)
            bsum += isf32 ? ((const float*)biasr)[c]
                          : __half2float(((const __half*)biasr)[c]);
        // s counts each pooled cell twice -> /2; then /POOL_COUNT; then /2
        out[b] = sm[0] / (4.0f * POOL_COUNT) + bsum;
    }
}

// ---------------------------------------------------------------------------
extern "C" void kernel_launch(void* const* d_in, const int* in_sizes, int n_in,
                              void* d_out, int out_size)
{
    int ix = -1, iw = -1, i16a = -1, i16b = -1;
    for (int i = 0; i < n_in; ++i) {
        if (in_sizes[i] == X_ELEMS) ix = i;
        else if (in_sizes[i] == W_ELEMS) iw = i;
        else if (in_sizes[i] == N_CO) { if (i16a < 0) i16a = i; else i16b = i; }
    }
    int icb, ibias;
    if (ix >= 0 && iw >= 0 && i16a >= 0 && i16b >= 0) {
        int da = (i16a > iw) ? (i16a - iw) : (iw - i16a);
        int db2 = (i16b > iw) ? (i16b - iw) : (iw - i16b);
        if (da <= db2) { icb = i16a; ibias = i16b; }
        else           { icb = i16b; ibias = i16a; }
    } else {
        ix = 0; iw = 1; icb = 2; ibias = 3;
    }

    const void* x  = d_in[ix];
    const void* cw = d_in[iw];
    const void* cb = d_in[icb];
    const void* bs = d_in[ibias];
    float* out = (float*)d_out;

    static int smem_set = 0;
    if (!smem_set) {
        cudaFuncSetAttribute(conv_mma_kernel,
                             cudaFuncAttributeMaxDynamicSharedMemorySize,
                             SMEM_BYTES);
        smem_set = 1;
    }

    conv_mma_kernel<<<304, 192, SMEM_BYTES>>>(x, cw, cb);
    finalize_kernel<<<32, 64>>>(bs, out);
}